// round 10
// baseline (speedup 1.0000x reference)
#include <cuda_runtime.h>
#include <cuda_bf16.h>
#include <cstdint>

// Problem constants (shapes fixed by the dataset)
#define DD 128
#define NN 50000
#define EE 600000

// Scratch (no runtime allocation allowed). Referenced directly from device
// code — kernel_launch does nothing but launch kernels (clean graph capture).
__device__ __align__(16) float g_tmp1[NN * DD];   // layer buffers
__device__ __align__(16) float g_tmp2[NN * DD];
__device__ float g_norm[EE];      // per-edge normalized weight
__device__ float g_dis[NN];       // deg^{-1/2}
__device__ int   g_cnt[NN];       // in-degree counts
__device__ int   g_cursor[NN];    // fill cursors
__device__ int   g_off[NN + 1];   // CSR offsets (by destination)
__device__ int   g_eidx[EE];      // CSR edge ids

// ---------------------------------------------------------------------------
// Zero the two int bookkeeping arrays
// ---------------------------------------------------------------------------
__global__ void zero2_kernel(int n) {
    int i = blockIdx.x * blockDim.x + threadIdx.x;
    if (i < n) { g_cnt[i] = 0; g_cursor[i] = 0; }
}

// cnt[col]++ for every edge. adj is int32 [2, E]: row = adj[e], col = adj[E+e].
__global__ void count_kernel(const int* __restrict__ adj, int E, int N) {
    int e = blockIdx.x * blockDim.x + threadIdx.x;
    if (e < E) {
        int col = adj[E + e];
        if ((unsigned)col < (unsigned)N) atomicAdd(&g_cnt[col], 1);
    }
}

// Exclusive scan of cnt[0..N) into off[0..N], single block of 1024 threads.
__global__ __launch_bounds__(1024) void scan_kernel(int N) {
    __shared__ int s[1024];
    const int t = threadIdx.x;
    const int CH = (NN + 1023) / 1024;            // 49
    int base = t * CH;
    int sum = 0;
    for (int i = 0; i < CH; i++) {
        int idx = base + i;
        if (idx < N) sum += g_cnt[idx];
    }
    s[t] = sum;
    __syncthreads();
    // Hillis-Steele inclusive scan over per-thread partial sums
    for (int d = 1; d < 1024; d <<= 1) {
        int v = (t >= d) ? s[t - d] : 0;
        __syncthreads();
        s[t] += v;
        __syncthreads();
    }
    int start = (t == 0) ? 0 : s[t - 1];
    for (int i = 0; i < CH; i++) {
        int idx = base + i;
        if (idx < N) { g_off[idx] = start; start += g_cnt[idx]; }
    }
    if (t == 1023) g_off[N] = s[1023];
}

// Scatter edge ids into CSR slots
__global__ void fill_kernel(const int* __restrict__ adj, int E, int N) {
    int e = blockIdx.x * blockDim.x + threadIdx.x;
    if (e < E) {
        int col = adj[E + e];
        if ((unsigned)col < (unsigned)N) {
            int pos = atomicAdd(&g_cursor[col], 1);
            g_eidx[g_off[col] + pos] = e;
        }
    }
}

// Per-node degree via CSR (no atomics): dis[n] = deg>0 ? rsqrt(deg) : 0
__global__ __launch_bounds__(256) void degnorm_kernel(
    const float* __restrict__ ew, int N) {
    int g = blockIdx.x * blockDim.x + threadIdx.x;
    int n = g >> 5, lane = g & 31;
    if (n >= N) return;
    int j0 = g_off[n], j1 = g_off[n + 1];
    float sum = 0.f;
    for (int j = j0 + lane; j < j1; j += 32) sum += ew[g_eidx[j]];
#pragma unroll
    for (int d = 16; d; d >>= 1) sum += __shfl_xor_sync(0xFFFFFFFFu, sum, d);
    if (lane == 0) g_dis[n] = (sum > 0.f) ? rsqrtf(sum) : 0.f;
}

// norm[e] = dis[row] * w[e] * dis[col]
__global__ void norm_kernel(const int* __restrict__ adj,
                            const float* __restrict__ w, int E, int N) {
    int e = blockIdx.x * blockDim.x + threadIdx.x;
    if (e < E) {
        int row = adj[e];
        int col = adj[E + e];
        float dr = ((unsigned)row < (unsigned)N) ? g_dis[row] : 0.f;
        float dc = ((unsigned)col < (unsigned)N) ? g_dis[col] : 0.f;
        g_norm[e] = dr * w[e] * dc;
    }
}

// ---------------------------------------------------------------------------
// GEMM: C[M,128] = A[M,128] @ W[128,128], fp32.
// 64 rows x 128 cols per block, 256 threads, 8x4 register tile per thread.
// ---------------------------------------------------------------------------
__global__ __launch_bounds__(256) void gemm_kernel(
    const float* __restrict__ A, const float* __restrict__ W,
    float* __restrict__ C, int M) {
    __shared__ float xs[64][32];
    __shared__ float ws[32][128];

    int t = threadIdx.x;
    int tx = t & 31;
    int ty = t >> 5;
    int rowBase = blockIdx.x * 64;

    float acc[8][4];
#pragma unroll
    for (int r = 0; r < 8; r++)
#pragma unroll
        for (int c = 0; c < 4; c++) acc[r][c] = 0.f;

#pragma unroll
    for (int kc = 0; kc < 4; kc++) {
#pragma unroll
        for (int j = 0; j < 8; j++) {
            int idx = t + j * 256;
            int r = idx >> 5, k = idx & 31;
            int row = rowBase + r;
            xs[r][k] = (row < M) ? A[row * DD + kc * 32 + k] : 0.f;
        }
#pragma unroll
        for (int j = 0; j < 16; j++) {
            int idx = t + j * 256;
            int k = idx >> 7, c = idx & 127;
            ws[k][c] = W[(kc * 32 + k) * DD + c];
        }
        __syncthreads();

#pragma unroll
        for (int k = 0; k < 32; k++) {
            float4 wv = *(const float4*)&ws[k][tx * 4];
#pragma unroll
            for (int r = 0; r < 8; r++) {
                float a = xs[ty * 8 + r][k];
                acc[r][0] += a * wv.x;
                acc[r][1] += a * wv.y;
                acc[r][2] += a * wv.z;
                acc[r][3] += a * wv.w;
            }
        }
        __syncthreads();
    }

#pragma unroll
    for (int r = 0; r < 8; r++) {
        int row = rowBase + ty * 8 + r;
        if (row < M)
            *(float4*)&C[row * DD + tx * 4] =
                make_float4(acc[r][0], acc[r][1], acc[r][2], acc[r][3]);
    }
}

// ---------------------------------------------------------------------------
// CSR gather + fused epilogue. One warp per destination node; lane owns 4
// features. acc = sum_e norm[e] * src[row_e]; then relu(acc + b) (+ resid).
// No atomics. 2-edge manual pipelining for MLP.
// ---------------------------------------------------------------------------
template <bool RESID>
__global__ __launch_bounds__(256) void gather_kernel(
    const int* __restrict__ adj,
    const float* __restrict__ src, const float* __restrict__ bias,
    const float* __restrict__ resid,
    float* __restrict__ dst, int N, int E) {
    int g = blockIdx.x * blockDim.x + threadIdx.x;
    int n = g >> 5, lane = g & 31;
    if (n >= N) return;

    int j = g_off[n], jend = g_off[n + 1];
    float ax = 0.f, ay = 0.f, az = 0.f, aw = 0.f;
    const int fo = lane << 2;

    for (; j + 1 < jend; j += 2) {
        int e0 = g_eidx[j], e1 = g_eidx[j + 1];
        int r0 = adj[e0], r1 = adj[e1];
        if ((unsigned)r0 >= (unsigned)N) r0 = 0;
        if ((unsigned)r1 >= (unsigned)N) r1 = 0;
        float w0 = g_norm[e0], w1 = g_norm[e1];
        float4 v0 = *(const float4*)(src + (size_t)r0 * DD + fo);
        float4 v1 = *(const float4*)(src + (size_t)r1 * DD + fo);
        ax += w0 * v0.x; ay += w0 * v0.y; az += w0 * v0.z; aw += w0 * v0.w;
        ax += w1 * v1.x; ay += w1 * v1.y; az += w1 * v1.z; aw += w1 * v1.w;
    }
    if (j < jend) {
        int e0 = g_eidx[j];
        int r0 = adj[e0];
        if ((unsigned)r0 >= (unsigned)N) r0 = 0;
        float w0 = g_norm[e0];
        float4 v0 = *(const float4*)(src + (size_t)r0 * DD + fo);
        ax += w0 * v0.x; ay += w0 * v0.y; az += w0 * v0.z; aw += w0 * v0.w;
    }

    float4 b = *(const float4*)(bias + fo);
    ax = fmaxf(ax + b.x, 0.f);
    ay = fmaxf(ay + b.y, 0.f);
    az = fmaxf(az + b.z, 0.f);
    aw = fmaxf(aw + b.w, 0.f);
    if (RESID) {
        float4 rv = *(const float4*)(resid + (size_t)n * DD + fo);
        ax += rv.x; ay += rv.y; az += rv.z; aw += rv.w;
    }
    *(float4*)(dst + (size_t)n * DD + fo) = make_float4(ax, ay, az, aw);
}

// ---------------------------------------------------------------------------
extern "C" void kernel_launch(void* const* d_in, const int* in_sizes, int n_in,
                              void* d_out, int out_size) {
    const float* x   = (const float*)d_in[0];
    const int*   adj = (const int*)d_in[1];     // int32 [2, E] (JAX x64 disabled)
    const float* ew  = (const float*)d_in[2];
    const float* W1  = (const float*)d_in[3];
    const float* b1  = (const float*)d_in[4];
    const float* W2  = (const float*)d_in[5];
    const float* b2  = (const float*)d_in[6];
    float*       out = (float*)d_out;

    const int E = in_sizes[2];           // 600000 (edge_weights count)
    const int N = in_sizes[0] / DD;      // 50000

    const int TB = 256;
    dim3 blkE((E + TB - 1) / TB);
    dim3 blkN((N + TB - 1) / TB);
    dim3 blkW((N * 32 + TB - 1) / TB);   // warp-per-node kernels
    dim3 blkG((N + 63) / 64);

    // --- CSR build (by destination) ---
    zero2_kernel<<<blkN, TB>>>(N);
    count_kernel<<<blkE, TB>>>(adj, E, N);
    scan_kernel<<<1, 1024>>>(N);
    fill_kernel<<<blkE, TB>>>(adj, E, N);

    // --- Normalization ---
    degnorm_kernel<<<blkW, TB>>>(ew, N);
    norm_kernel<<<blkE, TB>>>(adj, ew, E, N);

    // --- Layer 1: tmp1 = x@W1 ; tmp2 = relu(gather(tmp1) + b1) ---
    gemm_kernel<<<blkG, TB>>>(x, W1, g_tmp1, N);
    gather_kernel<false><<<blkW, TB>>>(adj, g_tmp1, b1, nullptr, g_tmp2, N, E);

    // --- Layer 2: tmp1 = tmp2@W2 ; out = relu(gather(tmp1) + b2) + x ---
    gemm_kernel<<<blkG, TB>>>(g_tmp2, W2, g_tmp1, N);
    gather_kernel<true><<<blkW, TB>>>(adj, g_tmp1, b2, x, out, N, E);
}